// round 1
// baseline (speedup 1.0000x reference)
#include <cuda_runtime.h>

// Problem constants
#define NROWS 10000
#define NFEAT 3000
#define NHID  32
#define KCLUST 10
#define ALPHAF 0.2f

// GEMM tiling
#define MT 128
#define KC 32
#define GEMM_THREADS 128
#define SPLITS 4

// Scratch (allocations are forbidden; __device__ globals are the sanctioned path)
__device__ float g_part[SPLITS * NROWS * NHID];   // split-K partials
__device__ float g_support[NROWS * NHID];         // x @ W

// ---------------------------------------------------------------------------
// Packed fp32x2 helpers (sm_103a): doubles FFMA throughput vs scalar FFMA.
// ---------------------------------------------------------------------------
__device__ __forceinline__ void fma2(unsigned long long& acc,
                                     unsigned long long a,
                                     unsigned long long b) {
    asm volatile("fma.rn.f32x2 %0, %1, %2, %0;" : "+l"(acc) : "l"(a), "l"(b));
}

__device__ __forceinline__ unsigned long long pack2(float x) {
    unsigned long long r;
    asm("mov.b64 %0, {%1, %1};" : "=l"(r) : "f"(x));
    return r;
}

// ---------------------------------------------------------------------------
// Generic C[M,32] += A[M,Kd] @ B[Kd,32] with split-K.
//   - Block computes MT=128 rows x 32 cols over a contiguous chunk range.
//   - Thread tile: 4 rows x 8 cols as 16 f32x2 accumulators.
//   - Writes its partial to g_part[split].
//   - B == nullptr means "use g_support as B" (second GEMM).
// ---------------------------------------------------------------------------
__global__ void __launch_bounds__(GEMM_THREADS)
gemm_kernel(const float* __restrict__ A, const float* __restrict__ B,
            int M, int Kd, int lda, int chunks_per_split, int total_chunks)
{
    __shared__ float As[MT][KC + 1];   // stride 33: conflict-free column reads
    __shared__ float Bs[KC][36];       // stride 36: 16B-aligned, conflict-free

    const float* Bp = (B == nullptr) ? g_support : B;

    const int tid  = threadIdx.x;
    const int row0 = blockIdx.x * MT;
    const int split = blockIdx.y;
    const int c0 = split * chunks_per_split;
    int c1 = c0 + chunks_per_split;
    if (c1 > total_chunks) c1 = total_chunks;

    const int cg = tid & 3;    // col group: cols cg*8 .. cg*8+7
    const int rg = tid >> 2;   // row group: rows rg*4 .. rg*4+3

    unsigned long long acc[4][4];
#pragma unroll
    for (int i = 0; i < 4; i++)
#pragma unroll
        for (int p = 0; p < 4; p++) acc[i][p] = 0ULL;

    for (int c = c0; c < c1; c++) {
        const int k0 = c * KC;

        // ---- stage A tile [MT x KC] to registers (coalesced float4) ----
        float4 av[8];
#pragma unroll
        for (int i = 0; i < 8; i++) {
            int idx = tid + i * GEMM_THREADS;
            int r   = idx >> 3;          // 8 float4 per row (KC=32)
            int c4  = idx & 7;
            int grow = row0 + r; if (grow > M - 1) grow = M - 1;
            int gk = k0 + c4 * 4;
            if (gk + 3 < Kd) {
                av[i] = *reinterpret_cast<const float4*>(A + (size_t)grow * lda + gk);
            } else {
                float4 v;
                const float* ar = A + (size_t)grow * lda;
                v.x = (gk + 0 < Kd) ? ar[gk + 0] : 0.0f;
                v.y = (gk + 1 < Kd) ? ar[gk + 1] : 0.0f;
                v.z = (gk + 2 < Kd) ? ar[gk + 2] : 0.0f;
                v.w = (gk + 3 < Kd) ? ar[gk + 3] : 0.0f;
                av[i] = v;
            }
        }
        // ---- stage B tile [KC x 32] ----
        float4 bv[2];
#pragma unroll
        for (int i = 0; i < 2; i++) {
            int idx = tid + i * GEMM_THREADS;
            int br  = idx >> 3;
            int c4  = idx & 7;
            int gk  = k0 + br;
            if (gk < Kd)
                bv[i] = *reinterpret_cast<const float4*>(Bp + (size_t)gk * NHID + c4 * 4);
            else
                bv[i] = make_float4(0.f, 0.f, 0.f, 0.f);
        }

        __syncthreads();   // previous compute done reading smem

#pragma unroll
        for (int i = 0; i < 8; i++) {
            int idx = tid + i * GEMM_THREADS;
            int r   = idx >> 3;
            int c4  = idx & 7;
            As[r][c4 * 4 + 0] = av[i].x;   // scalar STS: conflict-free with stride 33
            As[r][c4 * 4 + 1] = av[i].y;
            As[r][c4 * 4 + 2] = av[i].z;
            As[r][c4 * 4 + 3] = av[i].w;
        }
#pragma unroll
        for (int i = 0; i < 2; i++) {
            int idx = tid + i * GEMM_THREADS;
            int br  = idx >> 3;
            int c4  = idx & 7;
            *reinterpret_cast<float4*>(&Bs[br][c4 * 4]) = bv[i];
        }

        __syncthreads();

        // ---- compute: 32 k-steps, 16 fma.f32x2 each ----
#pragma unroll
        for (int kk = 0; kk < KC; kk++) {
            unsigned long long b2[4];
#pragma unroll
            for (int p = 0; p < 4; p++)
                b2[p] = *reinterpret_cast<const unsigned long long*>(&Bs[kk][cg * 8 + 2 * p]);
#pragma unroll
            for (int i = 0; i < 4; i++) {
                unsigned long long a2 = pack2(As[rg * 4 + i][kk]);
#pragma unroll
                for (int p = 0; p < 4; p++)
                    fma2(acc[i][p], a2, b2[p]);
            }
        }
    }

    // ---- write split partial ----
    float* Pout = g_part + (size_t)split * NROWS * NHID;
#pragma unroll
    for (int i = 0; i < 4; i++) {
        int grow = row0 + rg * 4 + i;
        if (grow < M) {
#pragma unroll
            for (int p = 0; p < 4; p++)
                *reinterpret_cast<unsigned long long*>(
                    &Pout[(size_t)grow * NHID + cg * 8 + 2 * p]) = acc[i][p];
        }
    }
}

// ---------------------------------------------------------------------------
// Reduce split-K partials into g_support (after GEMM1).
// ---------------------------------------------------------------------------
__global__ void reduce_support_kernel(int n)
{
    int i = blockIdx.x * blockDim.x + threadIdx.x;
    if (i < n) {
        float s = 0.0f;
#pragma unroll
        for (int sp = 0; sp < SPLITS; sp++) s += g_part[(size_t)sp * NROWS * NHID + i];
        g_support[i] = s;
    }
}

// ---------------------------------------------------------------------------
// Fused epilogue: z = sum(partials) + b   (written to out_z)
//                 q = student-t soft assignment (written to out_q)
// One warp per row; lane == hidden index (NHID == 32 exactly).
// ---------------------------------------------------------------------------
__global__ void __launch_bounds__(256)
zq_kernel(const float* __restrict__ bias, const float* __restrict__ mu,
          float* __restrict__ out_z, float* __restrict__ out_q)
{
    int gwarp = (blockIdx.x * blockDim.x + threadIdx.x) >> 5;
    int lane  = threadIdx.x & 31;
    if (gwarp >= NROWS) return;

    float zv = 0.0f;
#pragma unroll
    for (int sp = 0; sp < SPLITS; sp++)
        zv += g_part[(size_t)sp * NROWS * NHID + (size_t)gwarp * NHID + lane];
    zv += bias[lane];
    out_z[(size_t)gwarp * NHID + lane] = zv;

    float qsum = 0.0f;
    float myq  = 0.0f;
#pragma unroll
    for (int j = 0; j < KCLUST; j++) {
        float diff = zv - mu[j * NHID + lane];
        float d2 = diff * diff;
#pragma unroll
        for (int o = 16; o > 0; o >>= 1)
            d2 += __shfl_xor_sync(0xffffffffu, d2, o);
        // q = (1 / (1 + d2/alpha + 1e-8))^(alpha+1) / 2, then row-normalize
        float t  = 1.0f / (1.0f + d2 * (1.0f / ALPHAF) + 1e-8f);
        float qj = powf(t, ALPHAF + 1.0f) * 0.5f;
        qsum += qj;
        if (lane == j) myq = qj;
    }
    if (lane < KCLUST)
        out_q[(size_t)gwarp * KCLUST + lane] = myq / qsum;
}

// ---------------------------------------------------------------------------
// Launch: GEMM1 (x@W) -> reduce -> GEMM2 (adj@support) -> fused z+q epilogue
// ---------------------------------------------------------------------------
extern "C" void kernel_launch(void* const* d_in, const int* in_sizes, int n_in,
                              void* d_out, int out_size)
{
    const float* x   = (const float*)d_in[0];   // [10000, 3000]
    const float* adj = (const float*)d_in[1];   // [10000, 10000]
    const float* W   = (const float*)d_in[2];   // [3000, 32]
    const float* b   = (const float*)d_in[3];   // [32]
    const float* mu  = (const float*)d_in[4];   // [10, 32]

    float* out   = (float*)d_out;
    float* out_z = out;                         // [10000, 32]
    float* out_q = out + (size_t)NROWS * NHID;  // [10000, 10]

    const int mtiles = (NROWS + MT - 1) / MT;   // 79

    // GEMM1: support = x @ W
    {
        int total_chunks = (NFEAT + KC - 1) / KC;                    // 94
        int cps = (total_chunks + SPLITS - 1) / SPLITS;              // 24
        dim3 grid(mtiles, SPLITS);
        gemm_kernel<<<grid, GEMM_THREADS>>>(x, W, NROWS, NFEAT, NFEAT, cps, total_chunks);
    }
    // reduce partials -> g_support
    {
        int n = NROWS * NHID;
        reduce_support_kernel<<<(n + 255) / 256, 256>>>(n);
    }
    // GEMM2: z_partial = adj @ support  (B = nullptr -> g_support)
    {
        int total_chunks = (NROWS + KC - 1) / KC;                    // 313
        int cps = (total_chunks + SPLITS - 1) / SPLITS;              // 79
        dim3 grid(mtiles, SPLITS);
        gemm_kernel<<<grid, GEMM_THREADS>>>(adj, nullptr, NROWS, NROWS, NROWS, cps, total_chunks);
    }
    // fused: z = partials + b ; q = normalized student-t
    {
        int nthreads = NROWS * 32;   // one warp per row
        zq_kernel<<<(nthreads + 255) / 256, 256>>>(b, mu, out_z, out_q);
    }
}

// round 3
// speedup vs baseline: 1.3608x; 1.3608x over previous
#include <cuda_runtime.h>
#include <cstdint>

// Problem constants
#define NROWS 10000
#define NFEAT 3000
#define NHID  32
#define KCLUST 10
#define ALPHAF 0.2f

// GEMM tiling
#define MT 256
#define KC 32
#define GEMM_THREADS 128
#define SPLITS 7

#define AS_STRIDE 36                      // floats per A row in smem (16B-aligned, conflict-free)
#define AS_FLOATS (MT * AS_STRIDE)        // 9216
#define BS_FLOATS (KC * NHID)             // 1024
#define SMEM_BYTES ((2 * AS_FLOATS + 2 * BS_FLOATS) * 4)   // 81920

// Scratch (__device__ globals are the sanctioned path; 16B-aligned for vector access)
__device__ __align__(16) float g_part[SPLITS * NROWS * NHID];
__device__ __align__(16) float g_support[NROWS * NHID];

// ---------------------------------------------------------------------------
// sm_103a packed fp32 helpers
// ---------------------------------------------------------------------------
__device__ __forceinline__ void fma2(unsigned long long& acc,
                                     unsigned long long a,
                                     unsigned long long b) {
    asm volatile("fma.rn.f32x2 %0, %1, %2, %0;" : "+l"(acc) : "l"(a), "l"(b));
}
__device__ __forceinline__ unsigned long long pack2(float x) {
    unsigned long long r;
    asm("mov.b64 %0, {%1, %1};" : "=l"(r) : "f"(x));
    return r;
}
__device__ __forceinline__ void cp_async16(uint32_t saddr, const void* gaddr, int src_bytes) {
    asm volatile("cp.async.cg.shared.global [%0], [%1], 16, %2;"
                 :: "r"(saddr), "l"(gaddr), "r"(src_bytes));
}
__device__ __forceinline__ uint32_t smem_u32(const void* p) {
    return (uint32_t)__cvta_generic_to_shared(p);
}

// ---------------------------------------------------------------------------
// C[M,32] partial = A[M,Kd] @ B[Kd,32] over a split-K chunk range.
// MT=256 rows/block, 128 threads, thread tile 8 rows x 8 cols (f32x2 col pairs).
// cp.async double-buffered smem pipeline. Partials -> g_part[split].
// B == nullptr means B = g_support (second GEMM).
// ---------------------------------------------------------------------------
__global__ void __launch_bounds__(GEMM_THREADS)
gemm_kernel(const float* __restrict__ A, const float* __restrict__ B,
            int M, int Kd, int lda, int cps, int total_chunks)
{
    extern __shared__ float sm[];
    float* As0 = sm;                       // 2 buffers of [MT][AS_STRIDE]
    float* Bs0 = sm + 2 * AS_FLOATS;       // 2 buffers of [KC][NHID]

    const float* Bp = (B == nullptr) ? g_support : B;

    const int tid   = threadIdx.x;
    const int row0  = blockIdx.x * MT;
    const int split = blockIdx.y;
    const int c0    = split * cps;
    int c1 = c0 + cps;
    if (c1 > total_chunks) c1 = total_chunks;

    const int rt = tid >> 2;   // 0..31 : thread handles rows rt + 32*i, i=0..7
    const int cg = tid & 3;    // cols cg*8 .. cg*8+7

    unsigned long long acc[8][4];
#pragma unroll
    for (int i = 0; i < 8; i++)
#pragma unroll
        for (int p = 0; p < 4; p++) acc[i][p] = 0ULL;

    // ---- async stage of one chunk into buffer `buf` ----
    auto load_chunk = [&](int buf, int c) {
        const int k0 = c * KC;
        float* As = As0 + buf * AS_FLOATS;
        float* Bs = Bs0 + buf * BS_FLOATS;
        // A tile: 256 rows x 32 k = 2048 float4 -> 16 per thread, coalesced
#pragma unroll
        for (int t = 0; t < 16; t++) {
            int idx  = tid + t * GEMM_THREADS;
            int r    = idx >> 3;
            int c4   = idx & 7;
            int grow = row0 + r; if (grow > M - 1) grow = M - 1;
            int gk   = k0 + c4 * 4;
            int rem  = Kd - gk;
            int bytes = rem >= 4 ? 16 : (rem > 0 ? rem * 4 : 0);
            const float* src = (bytes > 0) ? (A + (size_t)grow * lda + gk) : A;
            cp_async16(smem_u32(As + r * AS_STRIDE + c4 * 4), src, bytes);
        }
        // B tile: 32 k x 32 cols = 256 float4 -> 2 per thread
#pragma unroll
        for (int t = 0; t < 2; t++) {
            int idx = tid + t * GEMM_THREADS;
            int br  = idx >> 3;
            int c4  = idx & 7;
            int gk  = k0 + br;
            int bytes = (gk < Kd) ? 16 : 0;
            const float* src = bytes ? (Bp + (size_t)gk * NHID + c4 * 4) : Bp;
            cp_async16(smem_u32(Bs + br * NHID + c4 * 4), src, bytes);
        }
        asm volatile("cp.async.commit_group;");
    };

    if (c0 < c1) load_chunk(0, c0);

    int buf = 0;
    for (int c = c0; c < c1; c++) {
        const bool more = (c + 1 < c1);
        if (more) {
            load_chunk(buf ^ 1, c + 1);
            asm volatile("cp.async.wait_group 1;");   // chunk c landed
        } else {
            asm volatile("cp.async.wait_group 0;");
        }
        __syncthreads();

        const float* As = As0 + buf * AS_FLOATS;
        const float* Bs = Bs0 + buf * BS_FLOATS;

#pragma unroll 8
        for (int kk = 0; kk < KC; kk++) {
            unsigned long long b2[4];
#pragma unroll
            for (int p = 0; p < 4; p++)
                b2[p] = *reinterpret_cast<const unsigned long long*>(
                            Bs + kk * NHID + cg * 8 + 2 * p);
#pragma unroll
            for (int i = 0; i < 8; i++) {
                unsigned long long a2 = pack2(As[(rt + 32 * i) * AS_STRIDE + kk]);
#pragma unroll
                for (int p = 0; p < 4; p++)
                    fma2(acc[i][p], a2, b2[p]);
            }
        }
        __syncthreads();   // all done reading `buf` before it is refilled next iter
        buf ^= 1;
    }

    // ---- write split partial ----
    float* Pout = g_part + (size_t)split * NROWS * NHID;
#pragma unroll
    for (int i = 0; i < 8; i++) {
        int grow = row0 + rt + 32 * i;
        if (grow < M) {
#pragma unroll
            for (int p = 0; p < 4; p++)
                *reinterpret_cast<unsigned long long*>(
                    Pout + (size_t)grow * NHID + cg * 8 + 2 * p) = acc[i][p];
        }
    }
}

// ---------------------------------------------------------------------------
// Reduce split-K partials into g_support (after GEMM1). Vectorized float4.
// ---------------------------------------------------------------------------
__global__ void reduce_support_kernel(int n4)
{
    int i = blockIdx.x * blockDim.x + threadIdx.x;
    if (i < n4) {
        float4 s = make_float4(0.f, 0.f, 0.f, 0.f);
#pragma unroll
        for (int sp = 0; sp < SPLITS; sp++) {
            float4 v = *reinterpret_cast<const float4*>(
                g_part + (size_t)sp * NROWS * NHID + (size_t)i * 4);
            s.x += v.x; s.y += v.y; s.z += v.z; s.w += v.w;
        }
        *reinterpret_cast<float4*>(g_support + (size_t)i * 4) = s;
    }
}

// ---------------------------------------------------------------------------
// Fused epilogue, one THREAD per row (no shuffles):
//   z = sum(partials) + b  -> out_z ;  q = normalized student-t -> out_q
// ---------------------------------------------------------------------------
__global__ void __launch_bounds__(128)
zq_kernel(const float* __restrict__ bias, const float* __restrict__ mu,
          float* __restrict__ out_z, float* __restrict__ out_q)
{
    int row = blockIdx.x * blockDim.x + threadIdx.x;
    if (row >= NROWS) return;

    float z[NHID];
#pragma unroll
    for (int k = 0; k < NHID; k += 4) {
        float4 s = make_float4(0.f, 0.f, 0.f, 0.f);
#pragma unroll
        for (int sp = 0; sp < SPLITS; sp++) {
            float4 v = *reinterpret_cast<const float4*>(
                g_part + (size_t)sp * NROWS * NHID + (size_t)row * NHID + k);
            s.x += v.x; s.y += v.y; s.z += v.z; s.w += v.w;
        }
        float4 bb = *reinterpret_cast<const float4*>(bias + k);
        s.x += bb.x; s.y += bb.y; s.z += bb.z; s.w += bb.w;
        z[k] = s.x; z[k + 1] = s.y; z[k + 2] = s.z; z[k + 3] = s.w;
        *reinterpret_cast<float4*>(out_z + (size_t)row * NHID + k) = s;
    }

    float q[KCLUST];
    float qsum = 0.0f;
#pragma unroll
    for (int j = 0; j < KCLUST; j++) {
        float d2 = 0.0f;
#pragma unroll
        for (int k = 0; k < NHID; k++) {
            float d = z[k] - __ldg(mu + j * NHID + k);
            d2 = fmaf(d, d, d2);
        }
        float t  = 1.0f / (1.0f + d2 * (1.0f / ALPHAF) + 1e-8f);
        float qj = __powf(t, ALPHAF + 1.0f) * 0.5f;
        q[j] = qj;
        qsum += qj;
    }
    float inv = 1.0f / qsum;
#pragma unroll
    for (int j = 0; j < KCLUST; j++)
        out_q[(size_t)row * KCLUST + j] = q[j] * inv;
}

// ---------------------------------------------------------------------------
// Launch: GEMM1 (x@W) -> reduce -> GEMM2 (adj@support) -> fused z+q epilogue
// ---------------------------------------------------------------------------
extern "C" void kernel_launch(void* const* d_in, const int* in_sizes, int n_in,
                              void* d_out, int out_size)
{
    const float* x   = (const float*)d_in[0];   // [10000, 3000]
    const float* adj = (const float*)d_in[1];   // [10000, 10000]
    const float* W   = (const float*)d_in[2];   // [3000, 32]
    const float* b   = (const float*)d_in[3];   // [32]
    const float* mu  = (const float*)d_in[4];   // [10, 32]

    float* out   = (float*)d_out;
    float* out_z = out;                          // [10000, 32]
    float* out_q = out + (size_t)NROWS * NHID;   // [10000, 10]

    // opt into >48KB dynamic smem (idempotent; not a stream op, capture-safe)
    cudaFuncSetAttribute(gemm_kernel,
                         cudaFuncAttributeMaxDynamicSharedMemorySize, SMEM_BYTES);

    const int mtiles = (NROWS + MT - 1) / MT;    // 40

    // GEMM1: partials of x @ W
    {
        int total_chunks = (NFEAT + KC - 1) / KC;             // 94
        int cps = (total_chunks + SPLITS - 1) / SPLITS;       // 14
        dim3 grid(mtiles, SPLITS);
        gemm_kernel<<<grid, GEMM_THREADS, SMEM_BYTES>>>(
            x, W, NROWS, NFEAT, NFEAT, cps, total_chunks);
    }
    // reduce partials -> g_support
    {
        int n4 = NROWS * NHID / 4;
        reduce_support_kernel<<<(n4 + 255) / 256, 256>>>(n4);
    }
    // GEMM2: partials of adj @ support (B = nullptr -> g_support)
    {
        int total_chunks = (NROWS + KC - 1) / KC;             // 313
        int cps = (total_chunks + SPLITS - 1) / SPLITS;       // 45
        dim3 grid(mtiles, SPLITS);
        gemm_kernel<<<grid, GEMM_THREADS, SMEM_BYTES>>>(
            adj, nullptr, NROWS, NROWS, NROWS, cps, total_chunks);
    }
    // fused: z = partials + b ; q = normalized student-t
    zq_kernel<<<(NROWS + 127) / 128, 128>>>(b, mu, out_z, out_q);
}